// round 1
// baseline (speedup 1.0000x reference)
#include <cuda_runtime.h>
#include <math.h>

#define BATCH 4
#define SEQ   1024
#define HID   768
#define HEADS 12
#define NENT  32
#define MENT  4
#define WD    768
#define AD    256
#define NC    97
#define SPLITK 64
#define DD    12
#define PP    144          // DD*DD
#define NPAIR (NENT*NENT)  // 1024

// ---------------- device scratch (no cudaMalloc allowed) ----------------
__device__ float d_rep[BATCH*NENT*HID];
__device__ float d_rs [BATCH*NENT*WD];
__device__ float d_ro [BATCH*NENT*WD];
__device__ float d_ga [BATCH*NENT*HEADS*SEQ];
__device__ float d_pa [(size_t)BATCH*NPAIR*SEQ];
__device__ float d_ctxh[(size_t)BATCH*NPAIR*HID];
__device__ float d_ctx[(size_t)BATCH*NPAIR*WD];
__device__ float d_Zs [(size_t)BATCH*NPAIR*WD];
__device__ float d_Zo [(size_t)BATCH*NPAIR*WD];
__device__ float d_P  [(size_t)BATCH*NPAIR*PP];
__device__ float d_g  [(size_t)BATCH*NPAIR*WD];
__device__ float d_t  [(size_t)BATCH*NPAIR*AD];
__device__ float d_e  [BATCH*NPAIR];
__device__ float d_arow[BATCH*NPAIR];
__device__ float d_acol[BATCH*NPAIR];
__device__ float d_rc [2*BATCH*NENT*WD];      // rowctx then colctx
__device__ float d_Ablt[PP*WD];
__device__ float d_gclf[(size_t)BATCH*NPAIR*NC];
__device__ float d_rgcg[2*BATCH*NENT*NC];

// ---------------- generic tiled fp32 SGEMM: C = A[MxK] * B[KxN] (+ scale*bias[n]) ----------------
__global__ __launch_bounds__(256)
void sgemm_kernel(const float* __restrict__ A, const float* __restrict__ Bm,
                  float* __restrict__ C, int M, int N, int K,
                  long long sA, long long sB, long long sC,
                  const float* __restrict__ bias, float biasScale)
{
    const int BM = 64, BN = 64, BK = 16;
    __shared__ float As[BK][BM + 4];
    __shared__ float Bs[BK][BN];
    int z = blockIdx.z;
    A  += (long long)z * sA;
    Bm += (long long)z * sB;
    C  += (long long)z * sC;
    int row0 = blockIdx.y * BM;
    int col0 = blockIdx.x * BN;
    int tid = threadIdx.x;
    int tx = tid & 15, ty = tid >> 4;

    float acc[4][4] = {};
    for (int k0 = 0; k0 < K; k0 += BK) {
        #pragma unroll
        for (int l = tid; l < BM * BK; l += 256) {
            int m = l >> 4, k = l & 15;
            int gm = row0 + m, gk = k0 + k;
            As[k][m] = (gm < M && gk < K) ? A[(long long)gm * K + gk] : 0.f;
        }
        #pragma unroll
        for (int l = tid; l < BK * BN; l += 256) {
            int k = l >> 6, n = l & 63;
            int gk = k0 + k, gn = col0 + n;
            Bs[k][n] = (gk < K && gn < N) ? Bm[(long long)gk * N + gn] : 0.f;
        }
        __syncthreads();
        #pragma unroll
        for (int k = 0; k < BK; k++) {
            float a[4], b[4];
            #pragma unroll
            for (int i = 0; i < 4; i++) a[i] = As[k][ty * 4 + i];
            #pragma unroll
            for (int j = 0; j < 4; j++) b[j] = Bs[k][tx * 4 + j];
            #pragma unroll
            for (int i = 0; i < 4; i++)
                #pragma unroll
                for (int j = 0; j < 4; j++)
                    acc[i][j] += a[i] * b[j];
        }
        __syncthreads();
    }
    #pragma unroll
    for (int i = 0; i < 4; i++) {
        int gm = row0 + ty * 4 + i;
        if (gm >= M) continue;
        #pragma unroll
        for (int j = 0; j < 4; j++) {
            int gn = col0 + tx * 4 + j;
            if (gn >= N) continue;
            float v = acc[i][j];
            if (bias) v += biasScale * bias[gn];
            C[(long long)gm * N + gn] = v;
        }
    }
}

// ---------------- stage kernels ----------------
__global__ void rep_kernel(const float* __restrict__ seq, const int* __restrict__ ep)
{
    int bn = blockIdx.x;
    int b = bn / NENT, n = bn % NENT;
    int e0 = ep[(b * NENT + n) * MENT + 0];
    int e1 = ep[(b * NENT + n) * MENT + 1];
    int e2 = ep[(b * NENT + n) * MENT + 2];
    int e3 = ep[(b * NENT + n) * MENT + 3];
    const float* sb = seq + (long long)b * SEQ * HID;
    for (int h = threadIdx.x; h < HID; h += blockDim.x) {
        float v0 = sb[(long long)e0 * HID + h];
        float v1 = sb[(long long)e1 * HID + h];
        float v2 = sb[(long long)e2 * HID + h];
        float v3 = sb[(long long)e3 * HID + h];
        float m = fmaxf(fmaxf(v0, v1), fmaxf(v2, v3));
        float s = expf(v0 - m) + expf(v1 - m) + expf(v2 - m) + expf(v3 - m);
        d_rep[(b * NENT + n) * HID + h] = m + logf(s);
    }
}

__global__ void ga_kernel(const float* __restrict__ att, const int* __restrict__ ep)
{
    int b = blockIdx.z;
    int n = blockIdx.y / HEADS, h = blockIdx.y % HEADS;
    int s = blockIdx.x * blockDim.x + threadIdx.x;
    const float* ab = att + ((long long)(b * HEADS + h)) * SEQ * SEQ;
    float a = 0.f;
    #pragma unroll
    for (int m = 0; m < MENT; m++) {
        int e = ep[(b * NENT + n) * MENT + m];
        a += ab[(long long)e * SEQ + s];
    }
    d_ga[((long long)((b * NENT + n) * HEADS + h)) * SEQ + s] = a;
}

__global__ __launch_bounds__(256) void pa_kernel()
{
    int b = blockIdx.y;
    int ij = blockIdx.x;
    int i = ij >> 5, j = ij & 31;
    const float* gi = d_ga + ((long long)(b * NENT + i)) * HEADS * SEQ;
    const float* gj = d_ga + ((long long)(b * NENT + j)) * HEADS * SEQ;
    int tid = threadIdx.x;
    float acc[4];
    float lsum = 0.f;
    #pragma unroll
    for (int r = 0; r < 4; r++) {
        int s = r * 256 + tid;
        float a = 0.f;
        #pragma unroll
        for (int h = 0; h < HEADS; h++)
            a += gi[h * SEQ + s] * gj[h * SEQ + s];
        acc[r] = a;
        lsum += a;
    }
    __shared__ float red[256];
    red[tid] = lsum;
    __syncthreads();
    for (int off = 128; off > 0; off >>= 1) {
        if (tid < off) red[tid] += red[tid + off];
        __syncthreads();
    }
    float inv = 1.0f / red[0];
    float* po = d_pa + ((long long)(b * NPAIR + ij)) * SEQ;
    #pragma unroll
    for (int r = 0; r < 4; r++)
        po[r * 256 + tid] = acc[r] * inv;
}

__global__ void zs_kernel()
{
    long long idx = (long long)blockIdx.x * blockDim.x + threadIdx.x;
    if (idx >= (long long)BATCH * NPAIR * WD) return;
    int w = (int)(idx % WD);
    long long t = idx / WD;
    int ij = (int)(t % NPAIR);
    int b = (int)(t / NPAIR);
    int i = ij >> 5;
    float c = d_ctx[idx];
    d_Zs[idx] = tanhf(d_rs[(b * NENT + i) * WD + w] + c);
    d_Zo[idx] = tanhf(d_ro[(b * NENT + i) * WD + w] + c);
}

__global__ __launch_bounds__(256) void P_kernel()
{
    __shared__ float zs[WD], zo[WD];
    long long row = blockIdx.x;
    for (int w = threadIdx.x; w < WD; w += 256) {
        zs[w] = d_Zs[row * WD + w];
        zo[w] = d_Zo[row * WD + w];
    }
    __syncthreads();
    int t = threadIdx.x;
    if (t < PP) {
        int p = t / DD, q = t % DD;
        float a = 0.f;
        #pragma unroll
        for (int k = 0; k < SPLITK; k++)
            a += zs[p * SPLITK + k] * zo[q * SPLITK + k];
        d_P[row * PP + t] = a;
    }
}

__global__ void transA_kernel(const float* __restrict__ A_bl)
{
    int idx = blockIdx.x * blockDim.x + threadIdx.x;
    if (idx >= WD * PP) return;
    int o = idx / PP, pq = idx % PP;
    d_Ablt[pq * WD + o] = A_bl[idx];
}

__global__ __launch_bounds__(256) void e_kernel(const float* __restrict__ v_attn)
{
    int row = blockIdx.x;
    int tid = threadIdx.x;
    float val = tanhf(d_t[(long long)row * AD + tid]) * v_attn[tid];
    __shared__ float red[256];
    red[tid] = val;
    __syncthreads();
    for (int off = 128; off > 0; off >>= 1) {
        if (tid < off) red[tid] += red[tid + off];
        __syncthreads();
    }
    if (tid == 0) d_e[row] = red[0];
}

__global__ __launch_bounds__(1024) void softmax_kernel()
{
    int b = blockIdx.x;
    int tid = threadIdx.x;
    int w = tid >> 5, lane = tid & 31;
    const float* eb = d_e + b * NPAIR;
    // row softmax (over j) for row i = w
    float v = eb[w * 32 + lane];
    float m = v;
    for (int o = 16; o > 0; o >>= 1) m = fmaxf(m, __shfl_xor_sync(~0u, m, o));
    float ex = expf(v - m);
    float s = ex;
    for (int o = 16; o > 0; o >>= 1) s += __shfl_xor_sync(~0u, s, o);
    d_arow[b * NPAIR + w * 32 + lane] = ex / s;
    // col softmax (over i) for col j = w
    float v2 = eb[lane * 32 + w];
    float m2 = v2;
    for (int o = 16; o > 0; o >>= 1) m2 = fmaxf(m2, __shfl_xor_sync(~0u, m2, o));
    float ex2 = expf(v2 - m2);
    float s2 = ex2;
    for (int o = 16; o > 0; o >>= 1) s2 += __shfl_xor_sync(~0u, s2, o);
    d_acol[b * NPAIR + lane * 32 + w] = ex2 / s2;
}

__global__ void rowcol_kernel()
{
    int b = blockIdx.z, nn = blockIdx.y;
    int w = blockIdx.x * blockDim.x + threadIdx.x;
    const float* gb = d_g + (long long)b * NPAIR * WD;
    float rsum = 0.f, csum = 0.f;
    #pragma unroll 4
    for (int k = 0; k < NENT; k++) {
        rsum += d_arow[b * NPAIR + nn * 32 + k] * gb[(long long)(nn * 32 + k) * WD + w];
        csum += d_acol[b * NPAIR + k * 32 + nn] * gb[(long long)(k * 32 + nn) * WD + w];
    }
    d_rc[((long long)(b * NENT + nn)) * WD + w] = rsum;
    d_rc[((long long)(BATCH * NENT + b * NENT + nn)) * WD + w] = csum;
}

__global__ void final_kernel(const float* __restrict__ clf_b, float* __restrict__ out)
{
    long long idx = (long long)blockIdx.x * blockDim.x + threadIdx.x;
    const long long total = (long long)BATCH * NPAIR * NC;
    if (idx >= total) return;
    int c = (int)(idx % NC);
    long long rb = idx / NC;
    int ij = (int)(rb % NPAIR);
    int b = (int)(rb / NPAIR);
    int i = ij >> 5, j = ij & 31;
    float v = d_gclf[idx]
            + d_rgcg[(b * NENT + i) * NC + c]
            + d_rgcg[(BATCH * NENT + b * NENT + j) * NC + c]
            + clf_b[c];
    out[idx] = v;
}

// ---------------- host launch ----------------
static void run_sgemm(const float* A, const float* Bm, float* C,
                      int M, int N, int K,
                      long long sA, long long sB, long long sC, int batch,
                      const float* bias, float biasScale)
{
    dim3 grid((N + 63) / 64, (M + 63) / 64, batch);
    sgemm_kernel<<<grid, 256>>>(A, Bm, C, M, N, K, sA, sB, sC, bias, biasScale);
}

extern "C" void kernel_launch(void* const* d_in, const int* in_sizes, int n_in,
                              void* d_out, int out_size)
{
    const float* seq    = (const float*)d_in[0];
    const float* att    = (const float*)d_in[1];
    const int*   ep     = (const int*)  d_in[2];
    const float* W_s    = (const float*)d_in[3];
    const float* W_o    = (const float*)d_in[4];
    const float* W_c    = (const float*)d_in[5];
    const float* A_bl   = (const float*)d_in[6];
    const float* b_bl   = (const float*)d_in[7];
    const float* W_attn = (const float*)d_in[8];
    const float* v_attn = (const float*)d_in[9];
    const float* clf_W  = (const float*)d_in[10];
    const float* clf_b  = (const float*)d_in[11];
    float* out = (float*)d_out;

    float *p_rep, *p_rs, *p_ro, *p_pa, *p_ctxh, *p_ctx, *p_P, *p_Ablt, *p_g,
          *p_t, *p_rc, *p_gclf, *p_rgcg;
    cudaGetSymbolAddress((void**)&p_rep,  d_rep);
    cudaGetSymbolAddress((void**)&p_rs,   d_rs);
    cudaGetSymbolAddress((void**)&p_ro,   d_ro);
    cudaGetSymbolAddress((void**)&p_pa,   d_pa);
    cudaGetSymbolAddress((void**)&p_ctxh, d_ctxh);
    cudaGetSymbolAddress((void**)&p_ctx,  d_ctx);
    cudaGetSymbolAddress((void**)&p_P,    d_P);
    cudaGetSymbolAddress((void**)&p_Ablt, d_Ablt);
    cudaGetSymbolAddress((void**)&p_g,    d_g);
    cudaGetSymbolAddress((void**)&p_t,    d_t);
    cudaGetSymbolAddress((void**)&p_rc,   d_rc);
    cudaGetSymbolAddress((void**)&p_gclf, d_gclf);
    cudaGetSymbolAddress((void**)&p_rgcg, d_rgcg);

    // 1. entity reps (logsumexp pooling)
    rep_kernel<<<BATCH * NENT, 256>>>(seq, ep);

    // 2. rs = rep @ W_s, ro = rep @ W_o  [128,768]x[768,768]
    run_sgemm(p_rep, W_s, p_rs, BATCH * NENT, WD, HID, 0, 0, 0, 1, nullptr, 0.f);
    run_sgemm(p_rep, W_o, p_ro, BATCH * NENT, WD, HID, 0, 0, 0, 1, nullptr, 0.f);

    // 3. transpose A_bl -> [144, 768]
    transA_kernel<<<(WD * PP + 255) / 256, 256>>>(A_bl);

    // 4. entity attention gather
    {
        dim3 grid(SEQ / 256, NENT * HEADS, BATCH);
        ga_kernel<<<grid, 256>>>(att, ep);
    }

    // 5. pairwise localized attention, normalized
    {
        dim3 grid(NPAIR, BATCH);
        pa_kernel<<<grid, 256>>>();
    }

    // 6. ctxh = pa @ seq   (batched per doc) [1024,1024]x[1024,768]
    run_sgemm(p_pa, seq, p_ctxh, NPAIR, HID, SEQ,
              (long long)NPAIR * SEQ, (long long)SEQ * HID, (long long)NPAIR * HID,
              BATCH, nullptr, 0.f);

    // 7. ctx = ctxh @ W_c   [4096,768]x[768,768]
    run_sgemm(p_ctxh, W_c, p_ctx, BATCH * NPAIR, WD, HID, 0, 0, 0, 1, nullptr, 0.f);

    // 8. Zs/Zo = tanh(rs/ro[i] + ctx)
    {
        long long total = (long long)BATCH * NPAIR * WD;
        zs_kernel<<<(unsigned)((total + 255) / 256), 256>>>();
    }

    // 9. P[i,j,p,q] = sum_k Zs4 * Zo4
    P_kernel<<<BATCH * NPAIR, 256>>>();

    // 10. g = P @ A_bl^T + 64*b_bl   [4096,144]x[144,768]
    run_sgemm(p_P, p_Ablt, p_g, BATCH * NPAIR, WD, PP, 0, 0, 0, 1, b_bl, (float)SPLITK);

    // 11. t = g @ W_attn   [4096,768]x[768,256]
    run_sgemm(p_g, W_attn, p_t, BATCH * NPAIR, AD, WD, 0, 0, 0, 1, nullptr, 0.f);

    // 12. e = tanh(t) . v_attn
    e_kernel<<<BATCH * NPAIR, 256>>>(v_attn);

    // 13. row/col softmax
    softmax_kernel<<<BATCH, 1024>>>();

    // 14. rowctx / colctx
    {
        dim3 grid(WD / 256, NENT, BATCH);
        rowcol_kernel<<<grid, 256>>>();
    }

    // 15. gclf = g @ clf_W ; rgcg = [rowctx;colctx] @ clf_W
    run_sgemm(p_g, clf_W, p_gclf, BATCH * NPAIR, NC, WD, 0, 0, 0, 1, nullptr, 0.f);
    run_sgemm(p_rc, clf_W, p_rgcg, 2 * BATCH * NENT, NC, WD, 0, 0, 0, 1, nullptr, 0.f);

    // 16. out = gclf + rg[i] + cg[j] + clf_b
    {
        long long total = (long long)BATCH * NPAIR * NC;
        final_kernel<<<(unsigned)((total + 255) / 256), 256>>>(clf_b, out);
    }
}

// round 2
// speedup vs baseline: 1.1402x; 1.1402x over previous
#include <cuda_runtime.h>
#include <math.h>

#define BATCH 4
#define SEQ   1024
#define HID   768
#define HEADS 12
#define NENT  32
#define MENT  4
#define WD    768
#define AD    256
#define NC    97
#define SPLITK 64
#define DD    12
#define PP    144          // DD*DD
#define NPAIR (NENT*NENT)  // 1024

// ---------------- device scratch ----------------
__device__ float d_rep[BATCH*NENT*HID];
__device__ float d_rs [BATCH*NENT*WD];
__device__ float d_ro [BATCH*NENT*WD];
__device__ float d_ga [BATCH*NENT*HEADS*SEQ];
__device__ float d_pa [(size_t)BATCH*NPAIR*SEQ];
__device__ float d_ctxh[(size_t)BATCH*NPAIR*HID];
__device__ float d_Zs [(size_t)BATCH*NPAIR*WD];
__device__ float d_Zo [(size_t)BATCH*NPAIR*WD];
__device__ float d_P  [(size_t)BATCH*NPAIR*PP];
__device__ float d_g  [(size_t)BATCH*NPAIR*WD];
__device__ float d_t  [(size_t)BATCH*NPAIR*AD];
__device__ float d_e  [BATCH*NPAIR];
__device__ float d_arow[BATCH*NPAIR];
__device__ float d_acol[BATCH*NPAIR];
__device__ float d_Ablt[PP*WD];
__device__ float d_gclf[(size_t)BATCH*NPAIR*NC];
__device__ float d_rgcg[2*BATCH*NENT*NC];
__device__ float d_part[1700000];   // split-K partials (max 4*4096*97 = 1,589,248)

// ---------------- tiled fp32 SGEMM ----------------
// C[M,N] = A[M,K] * B[K,N].  BM=128, BK=16, BN=16*TN, 256 threads, 8xTN microtile.
// kSplit slices K across blockIdx.z (writes partials at C + kz*partStride).
// MODE 0: optional C += biasScale*bias[n].
// MODE 1: C = tanh(acc + bias[(gm>>5)*N+gn]); C2 = tanh(acc + bias2[(gm>>5)*N+gn]).
// Requirements: M % 128 == 0, K/kSplit % 16 == 0, K % 4 == 0.
template<int TN, int MODE>
__global__ __launch_bounds__(256)
void sgemm_t(const float* __restrict__ A, const float* __restrict__ B,
             float* __restrict__ C, float* __restrict__ C2,
             int M, int N, int K,
             long long sA, long long sB, long long sC,
             int kSplit, long long partStride,
             const float* __restrict__ bias, float biasScale,
             const float* __restrict__ bias2)
{
    const int BM = 128, BK = 16, BN = 16 * TN;
    __shared__ float As[BK][BM + 4];   // padded: conflict relief + 16B-aligned rows
    __shared__ float Bs[BK][BN];

    int zb = blockIdx.z / kSplit;
    int kz = blockIdx.z - zb * kSplit;
    A += (long long)zb * sA;
    B += (long long)zb * sB;
    C += (long long)zb * sC + (long long)kz * partStride;

    int row0 = blockIdx.y * BM;
    int col0 = blockIdx.x * BN;
    int tid = threadIdx.x;
    int tx = tid & 15, ty = tid >> 4;

    int kLen = K / kSplit;
    int k0beg = kz * kLen, k0end = k0beg + kLen;

    float acc[8][TN];
    #pragma unroll
    for (int i = 0; i < 8; i++)
        #pragma unroll
        for (int j = 0; j < TN; j++) acc[i][j] = 0.f;

    const bool nvec = ((N & 3) == 0);

    for (int k0 = k0beg; k0 < k0end; k0 += BK) {
        // --- load A tile (128x16) via float4, stored transposed ---
        #pragma unroll
        for (int i = 0; i < 2; i++) {
            int l = tid + i * 256;
            int m = l >> 2, kq = (l & 3) * 4;
            float4 v = *(const float4*)(A + (long long)(row0 + m) * K + (k0 + kq));
            As[kq + 0][m] = v.x;
            As[kq + 1][m] = v.y;
            As[kq + 2][m] = v.z;
            As[kq + 3][m] = v.w;
        }
        // --- load B tile (16xBN) ---
        if (nvec) {
            #pragma unroll
            for (int l = tid; l < BK * BN / 4; l += 256) {
                int k = l / (BN / 4), nq = (l % (BN / 4)) * 4;
                int gn = col0 + nq;
                float4 v = make_float4(0.f, 0.f, 0.f, 0.f);
                if (gn < N) v = *(const float4*)(B + (long long)(k0 + k) * N + gn);
                *(float4*)&Bs[k][nq] = v;
            }
        } else {
            #pragma unroll
            for (int l = tid; l < BK * BN; l += 256) {
                int k = l / BN, n = l % BN;
                int gn = col0 + n;
                Bs[k][n] = (gn < N) ? B[(long long)(k0 + k) * N + gn] : 0.f;
            }
        }
        __syncthreads();
        // --- compute ---
        #pragma unroll
        for (int k = 0; k < BK; k++) {
            float a[8];
            {
                float4 v0 = *(const float4*)&As[k][ty * 8];
                float4 v1 = *(const float4*)&As[k][ty * 8 + 4];
                a[0] = v0.x; a[1] = v0.y; a[2] = v0.z; a[3] = v0.w;
                a[4] = v1.x; a[5] = v1.y; a[6] = v1.z; a[7] = v1.w;
            }
            float bf[TN];
            if (TN == 8) {
                float4 v0 = *(const float4*)&Bs[k][tx * 8];
                float4 v1 = *(const float4*)&Bs[k][tx * 8 + 4];
                bf[0] = v0.x; bf[1] = v0.y; bf[2] = v0.z; bf[3] = v0.w;
                bf[4 % TN] = v1.x; bf[5 % TN] = v1.y; bf[6 % TN] = v1.z; bf[7 % TN] = v1.w;
            } else if (TN == 4) {
                float4 v0 = *(const float4*)&Bs[k][tx * 4];
                bf[0] = v0.x; bf[1 % TN] = v0.y; bf[2 % TN] = v0.z; bf[3 % TN] = v0.w;
            } else {
                float2 v0 = *(const float2*)&Bs[k][tx * 2];
                bf[0] = v0.x; bf[1 % TN] = v0.y;
            }
            #pragma unroll
            for (int i = 0; i < 8; i++)
                #pragma unroll
                for (int j = 0; j < TN; j++)
                    acc[i][j] += a[i] * bf[j];
        }
        __syncthreads();
    }
    // --- epilogue ---
    #pragma unroll
    for (int i = 0; i < 8; i++) {
        int gm = row0 + ty * 8 + i;
        #pragma unroll
        for (int j = 0; j < TN; j++) {
            int gn = col0 + tx * TN + j;
            if (gn >= N) continue;
            float v = acc[i][j];
            if (MODE == 0) {
                if (bias) v += biasScale * bias[gn];
                C[(long long)gm * N + gn] = v;
            } else {
                long long br = (long long)(gm >> 5) * N + gn;
                C [(long long)gm * N + gn] = tanhf(v + bias[br]);
                C2[(long long)gm * N + gn] = tanhf(v + bias2[br]);
            }
        }
    }
}

__global__ void reduce_add_kernel(const float* __restrict__ src, float* __restrict__ dst,
                                  int parts, long long len)
{
    long long i = (long long)blockIdx.x * 256 + threadIdx.x;
    if (i >= len) return;
    float s = 0.f;
    for (int p = 0; p < parts; p++) s += src[(long long)p * len + i];
    dst[i] = s;
}

// ---------------- stage kernels ----------------
__global__ void rep_kernel(const float* __restrict__ seq, const int* __restrict__ ep)
{
    int bn = blockIdx.x;
    int b = bn / NENT, n = bn % NENT;
    int e0 = ep[(b * NENT + n) * MENT + 0];
    int e1 = ep[(b * NENT + n) * MENT + 1];
    int e2 = ep[(b * NENT + n) * MENT + 2];
    int e3 = ep[(b * NENT + n) * MENT + 3];
    const float* sb = seq + (long long)b * SEQ * HID;
    for (int h = threadIdx.x; h < HID; h += blockDim.x) {
        float v0 = sb[(long long)e0 * HID + h];
        float v1 = sb[(long long)e1 * HID + h];
        float v2 = sb[(long long)e2 * HID + h];
        float v3 = sb[(long long)e3 * HID + h];
        float m = fmaxf(fmaxf(v0, v1), fmaxf(v2, v3));
        float s = expf(v0 - m) + expf(v1 - m) + expf(v2 - m) + expf(v3 - m);
        d_rep[(b * NENT + n) * HID + h] = m + logf(s);
    }
}

__global__ void ga_kernel(const float* __restrict__ att, const int* __restrict__ ep)
{
    int b = blockIdx.z;
    int n = blockIdx.y / HEADS, h = blockIdx.y % HEADS;
    int s = blockIdx.x * blockDim.x + threadIdx.x;
    const float* ab = att + ((long long)(b * HEADS + h)) * SEQ * SEQ;
    float a = 0.f;
    #pragma unroll
    for (int m = 0; m < MENT; m++) {
        int e = ep[(b * NENT + n) * MENT + m];
        a += ab[(long long)e * SEQ + s];
    }
    d_ga[((long long)((b * NENT + n) * HEADS + h)) * SEQ + s] = a;
}

__global__ __launch_bounds__(256) void pa_kernel()
{
    int b = blockIdx.y;
    int ij = blockIdx.x;
    int i = ij >> 5, j = ij & 31;
    const float* gi = d_ga + ((long long)(b * NENT + i)) * HEADS * SEQ;
    const float* gj = d_ga + ((long long)(b * NENT + j)) * HEADS * SEQ;
    int tid = threadIdx.x;
    float acc[4];
    float lsum = 0.f;
    #pragma unroll
    for (int r = 0; r < 4; r++) {
        int s = r * 256 + tid;
        float a = 0.f;
        #pragma unroll
        for (int h = 0; h < HEADS; h++)
            a += gi[h * SEQ + s] * gj[h * SEQ + s];
        acc[r] = a;
        lsum += a;
    }
    __shared__ float red[256];
    red[tid] = lsum;
    __syncthreads();
    for (int off = 128; off > 0; off >>= 1) {
        if (tid < off) red[tid] += red[tid + off];
        __syncthreads();
    }
    float inv = 1.0f / red[0];
    float* po = d_pa + ((long long)(b * NPAIR + ij)) * SEQ;
    #pragma unroll
    for (int r = 0; r < 4; r++)
        po[r * 256 + tid] = acc[r] * inv;
}

__global__ __launch_bounds__(256) void P_kernel()
{
    __shared__ float zs[WD], zo[WD];
    long long row = blockIdx.x;
    for (int w = threadIdx.x; w < WD; w += 256) {
        zs[w] = d_Zs[row * WD + w];
        zo[w] = d_Zo[row * WD + w];
    }
    __syncthreads();
    int t = threadIdx.x;
    if (t < PP) {
        int p = t / DD, q = t % DD;
        float a = 0.f;
        #pragma unroll
        for (int k = 0; k < SPLITK; k++)
            a += zs[p * SPLITK + k] * zo[q * SPLITK + k];
        d_P[row * PP + t] = a;
    }
}

__global__ void transA_kernel(const float* __restrict__ A_bl)
{
    int idx = blockIdx.x * blockDim.x + threadIdx.x;
    if (idx >= WD * PP) return;
    int o = idx / PP, pq = idx % PP;
    d_Ablt[pq * WD + o] = A_bl[idx];
}

__global__ __launch_bounds__(256) void e_kernel(const float* __restrict__ v_attn)
{
    int row = blockIdx.x;
    int tid = threadIdx.x;
    float val = tanhf(d_t[(long long)row * AD + tid]) * v_attn[tid];
    __shared__ float red[256];
    red[tid] = val;
    __syncthreads();
    for (int off = 128; off > 0; off >>= 1) {
        if (tid < off) red[tid] += red[tid + off];
        __syncthreads();
    }
    if (tid == 0) d_e[row] = red[0];
}

__global__ __launch_bounds__(1024) void softmax_kernel()
{
    int b = blockIdx.x;
    int tid = threadIdx.x;
    int w = tid >> 5, lane = tid & 31;
    const float* eb = d_e + b * NPAIR;
    float v = eb[w * 32 + lane];
    float m = v;
    for (int o = 16; o > 0; o >>= 1) m = fmaxf(m, __shfl_xor_sync(~0u, m, o));
    float ex = expf(v - m);
    float s = ex;
    for (int o = 16; o > 0; o >>= 1) s += __shfl_xor_sync(~0u, s, o);
    d_arow[b * NPAIR + w * 32 + lane] = ex / s;
    float v2 = eb[lane * 32 + w];
    float m2 = v2;
    for (int o = 16; o > 0; o >>= 1) m2 = fmaxf(m2, __shfl_xor_sync(~0u, m2, o));
    float ex2 = expf(v2 - m2);
    float s2 = ex2;
    for (int o = 16; o > 0; o >>= 1) s2 += __shfl_xor_sync(~0u, s2, o);
    d_acol[b * NPAIR + lane * 32 + w] = ex2 / s2;
}

// rowctx@clf_W and colctx@clf_W via linearity: weighted sums over gclf.
__global__ void rowcolC_kernel()
{
    int b = blockIdx.y, n = blockIdx.x;
    int c = threadIdx.x;
    if (c >= NC) return;
    const float* gc = d_gclf + (long long)b * NPAIR * NC;
    float rs = 0.f, cs = 0.f;
    #pragma unroll 4
    for (int k = 0; k < NENT; k++) {
        rs += d_arow[b * NPAIR + n * 32 + k] * gc[(long long)(n * 32 + k) * NC + c];
        cs += d_acol[b * NPAIR + k * 32 + n] * gc[(long long)(k * 32 + n) * NC + c];
    }
    d_rgcg[(b * NENT + n) * NC + c] = rs;
    d_rgcg[(BATCH * NENT + b * NENT + n) * NC + c] = cs;
}

__global__ void final_kernel(const float* __restrict__ clf_b, float* __restrict__ out)
{
    long long idx = (long long)blockIdx.x * blockDim.x + threadIdx.x;
    const long long total = (long long)BATCH * NPAIR * NC;
    if (idx >= total) return;
    int c = (int)(idx % NC);
    long long rb = idx / NC;
    int ij = (int)(rb % NPAIR);
    int b = (int)(rb / NPAIR);
    int i = ij >> 5, j = ij & 31;
    out[idx] = d_gclf[idx]
             + d_rgcg[(b * NENT + i) * NC + c]
             + d_rgcg[(BATCH * NENT + b * NENT + j) * NC + c]
             + clf_b[c];
}

// ---------------- host launch ----------------
extern "C" void kernel_launch(void* const* d_in, const int* in_sizes, int n_in,
                              void* d_out, int out_size)
{
    const float* seq    = (const float*)d_in[0];
    const float* att    = (const float*)d_in[1];
    const int*   ep     = (const int*)  d_in[2];
    const float* W_s    = (const float*)d_in[3];
    const float* W_o    = (const float*)d_in[4];
    const float* W_c    = (const float*)d_in[5];
    const float* A_bl   = (const float*)d_in[6];
    const float* b_bl   = (const float*)d_in[7];
    const float* W_attn = (const float*)d_in[8];
    const float* v_attn = (const float*)d_in[9];
    const float* clf_W  = (const float*)d_in[10];
    const float* clf_b  = (const float*)d_in[11];
    float* out = (float*)d_out;

    float *p_rep, *p_rs, *p_ro, *p_pa, *p_ctxh, *p_Zs, *p_Zo, *p_P, *p_Ablt,
          *p_g, *p_t, *p_gclf, *p_part;
    cudaGetSymbolAddress((void**)&p_rep,  d_rep);
    cudaGetSymbolAddress((void**)&p_rs,   d_rs);
    cudaGetSymbolAddress((void**)&p_ro,   d_ro);
    cudaGetSymbolAddress((void**)&p_pa,   d_pa);
    cudaGetSymbolAddress((void**)&p_ctxh, d_ctxh);
    cudaGetSymbolAddress((void**)&p_Zs,   d_Zs);
    cudaGetSymbolAddress((void**)&p_Zo,   d_Zo);
    cudaGetSymbolAddress((void**)&p_P,    d_P);
    cudaGetSymbolAddress((void**)&p_Ablt, d_Ablt);
    cudaGetSymbolAddress((void**)&p_g,    d_g);
    cudaGetSymbolAddress((void**)&p_t,    d_t);
    cudaGetSymbolAddress((void**)&p_gclf, d_gclf);
    cudaGetSymbolAddress((void**)&p_part, d_part);

    // 1. entity reps
    rep_kernel<<<BATCH * NENT, 256>>>(seq, ep);

    // 2. rs = rep @ W_s (split-K 8), ro = rep @ W_o
    {
        dim3 grid(WD / 32, 1, 8);
        sgemm_t<2, 0><<<grid, 256>>>(p_rep, W_s, p_part, nullptr,
                                     BATCH * NENT, WD, HID, 0, 0, 0,
                                     8, (long long)BATCH * NENT * WD, nullptr, 0.f, nullptr);
        reduce_add_kernel<<<(BATCH * NENT * WD + 255) / 256, 256>>>(
            p_part, p_rs, 8, (long long)BATCH * NENT * WD);
        sgemm_t<2, 0><<<grid, 256>>>(p_rep, W_o, p_part, nullptr,
                                     BATCH * NENT, WD, HID, 0, 0, 0,
                                     8, (long long)BATCH * NENT * WD, nullptr, 0.f, nullptr);
        reduce_add_kernel<<<(BATCH * NENT * WD + 255) / 256, 256>>>(
            p_part, p_ro, 8, (long long)BATCH * NENT * WD);
    }

    // 3. transpose A_bl -> [144,768]
    transA_kernel<<<(WD * PP + 255) / 256, 256>>>(A_bl);

    // 4. entity attention gather
    {
        dim3 grid(SEQ / 256, NENT * HEADS, BATCH);
        ga_kernel<<<grid, 256>>>(att, ep);
    }

    // 5. pairwise localized attention (normalized)
    {
        dim3 grid(NPAIR, BATCH);
        pa_kernel<<<grid, 256>>>();
    }

    // 6. ctxh = pa @ seq  (batched) [1024,768,1024] x4
    {
        dim3 grid(WD / 128, NPAIR / 128, BATCH);
        sgemm_t<8, 0><<<grid, 256>>>(p_pa, seq, p_ctxh, nullptr,
                                     NPAIR, HID, SEQ,
                                     (long long)NPAIR * SEQ, (long long)SEQ * HID,
                                     (long long)NPAIR * HID,
                                     1, 0, nullptr, 0.f, nullptr);
    }

    // 7. fused: Zs/Zo = tanh(rs/ro[row>>5] + ctxh @ W_c)   [4096,768,768]
    {
        dim3 grid(WD / 128, (BATCH * NPAIR) / 128, 1);
        sgemm_t<8, 1><<<grid, 256>>>(p_ctxh, W_c, p_Zs, p_Zo,
                                     BATCH * NPAIR, WD, HID, 0, 0, 0,
                                     1, 0, p_rs, 0.f, p_ro);
    }

    // 8. P[i,j,p,q] = sum_k Zs4*Zo4
    P_kernel<<<BATCH * NPAIR, 256>>>();

    // 9. g = P @ A_bl^T + 64*b_bl   [4096,768,144]
    {
        dim3 grid(WD / 128, (BATCH * NPAIR) / 128, 1);
        sgemm_t<8, 0><<<grid, 256>>>(p_P, p_Ablt, p_g, nullptr,
                                     BATCH * NPAIR, WD, PP, 0, 0, 0,
                                     1, 0, b_bl, (float)SPLITK, nullptr);
    }

    // 10. t = g @ W_attn   [4096,256,768]
    {
        dim3 grid(AD / 64, (BATCH * NPAIR) / 128, 1);
        sgemm_t<4, 0><<<grid, 256>>>(p_g, W_attn, p_t, nullptr,
                                     BATCH * NPAIR, AD, WD, 0, 0, 0,
                                     1, 0, nullptr, 0.f, nullptr);
    }

    // 11. e = tanh(t) . v_attn
    e_kernel<<<BATCH * NPAIR, 256>>>(v_attn);

    // 12. row/col softmax
    softmax_kernel<<<BATCH, 1024>>>();

    // 13. gclf = g @ clf_W  (split-K 4)  [4096,97,768]
    {
        long long len = (long long)BATCH * NPAIR * NC;
        dim3 grid((NC + 31) / 32, (BATCH * NPAIR) / 128, 4);
        sgemm_t<2, 0><<<grid, 256>>>(p_g, clf_W, p_part, nullptr,
                                     BATCH * NPAIR, NC, WD, 0, 0, 0,
                                     4, len, nullptr, 0.f, nullptr);
        reduce_add_kernel<<<(unsigned)((len + 255) / 256), 256>>>(p_part, p_gclf, 4, len);
    }

    // 14. axis-attention residual folded through clf_W (linearity)
    {
        dim3 grid(NENT, BATCH);
        rowcolC_kernel<<<grid, 128>>>();
    }

    // 15. out = gclf + rg[i] + cg[j] + clf_b
    {
        long long total = (long long)BATCH * NPAIR * NC;
        final_kernel<<<(unsigned)((total + 255) / 256), 256>>>(clf_b, out);
    }
}

// round 3
// speedup vs baseline: 1.5211x; 1.3341x over previous
#include <cuda_runtime.h>
#include <math.h>
#include <stdint.h>

#define BATCH 4
#define SEQ   1024
#define HID   768
#define HEADS 12
#define NENT  32
#define MENT  4
#define WD    768
#define AD    256
#define NC    97
#define SPLITK 64
#define DD    12
#define PP    144          // DD*DD
#define NPAIR (NENT*NENT)  // 1024

// ---------------- device scratch ----------------
__device__ float d_rep[BATCH*NENT*HID];
__device__ float d_rso[BATCH*NENT*2*WD];          // [128][1536] : rs | ro
__device__ float d_Wso[WD*2*WD];                  // [768][1536] : W_s | W_o
__device__ float d_ga [BATCH*NENT*HEADS*SEQ];
__device__ float d_pa [(size_t)BATCH*NPAIR*SEQ];
__device__ float d_ctxh[(size_t)BATCH*NPAIR*HID];
__device__ float d_Zs [(size_t)BATCH*NPAIR*WD];
__device__ float d_Zo [(size_t)BATCH*NPAIR*WD];
__device__ float d_P  [(size_t)BATCH*NPAIR*PP];
__device__ float d_g  [(size_t)BATCH*NPAIR*WD];
__device__ float d_t  [(size_t)BATCH*NPAIR*AD];
__device__ float d_e  [BATCH*NPAIR];
__device__ float d_arow[BATCH*NPAIR];
__device__ float d_acol[BATCH*NPAIR];
__device__ float d_Ablt[PP*WD];
__device__ float d_gclf[(size_t)BATCH*NPAIR*NC];
__device__ float d_rgcg[2*BATCH*NENT*NC];
__device__ float d_part[1700000];                 // split-K partials

// ---------------- tf32 helpers ----------------
__device__ __forceinline__ uint32_t f2tf32(float x)
{
    uint32_t r;
    asm("cvt.rna.tf32.f32 %0, %1;" : "=r"(r) : "f"(x));
    return r;
}

__device__ __forceinline__ void mma_tf32(float* c, const uint32_t* a, const uint32_t* b)
{
    asm volatile(
        "mma.sync.aligned.m16n8k8.row.col.f32.tf32.tf32.f32 "
        "{%0,%1,%2,%3}, {%4,%5,%6,%7}, {%8,%9}, {%0,%1,%2,%3};"
        : "+f"(c[0]), "+f"(c[1]), "+f"(c[2]), "+f"(c[3])
        : "r"(a[0]), "r"(a[1]), "r"(a[2]), "r"(a[3]), "r"(b[0]), "r"(b[1]));
}

// ---------------- tf32 tensor-core GEMM ----------------
// C[M,N] = A[M,K] row-major * B[K,N] row-major.
// BM=128, BN=64, BK=16. 256 threads = 8 warps (4 m-warps x 2 n-warps),
// warp tile 32x32 = 2 m16-tiles x 4 n8-tiles. Operands staged in smem in
// mma fragment order (tf32-converted at gmem->smem time).
// MODE 0: C = acc (+ biasScale*bias[n] if bias).
// MODE 1: C = tanh(acc + bias[(gm>>5)*biasStride+gn]); C2 likewise with bias2.
// Requirements: M%128==0, K/kSplit %16==0.
template<int MODE>
__global__ __launch_bounds__(256)
void mma_gemm(const float* __restrict__ A, const float* __restrict__ B,
              float* __restrict__ C, float* __restrict__ C2,
              int M, int N, int K,
              long long sA, long long sB, long long sC,
              int kSplit, long long partStride,
              const float* __restrict__ bias, float biasScale,
              const float* __restrict__ bias2, int biasStride)
{
    __shared__ uint32_t As[2 * 8 * 32 * 4];   // [k8][mt][lane][4]  8KB
    __shared__ uint32_t Bs[2 * 8 * 32 * 2];   // [k8][nt][lane][2]  4KB

    int zb = blockIdx.z / kSplit;
    int kz = blockIdx.z - zb * kSplit;
    A += (long long)zb * sA;
    B += (long long)zb * sB;
    C += (long long)zb * sC + (long long)kz * partStride;

    int row0 = blockIdx.y * 128;
    int col0 = blockIdx.x * 64;
    int tid = threadIdx.x, lane = tid & 31, w = tid >> 5;
    int wm = w & 3, wn = w >> 2;
    int groupID = lane >> 2, tig = lane & 3;

    int kLen = K / kSplit;
    int k0beg = kz * kLen, k0end = k0beg + kLen;

    float acc[2][4][4];
    #pragma unroll
    for (int i = 0; i < 2; i++)
        #pragma unroll
        for (int j = 0; j < 4; j++)
            #pragma unroll
            for (int r = 0; r < 4; r++) acc[i][j][r] = 0.f;

    const bool nvec = ((N & 3) == 0);

    for (int k0 = k0beg; k0 < k0end; k0 += 16) {
        // ---- A tile 128x16 -> fragment-order smem (2 float4 per thread) ----
        #pragma unroll
        for (int i = 0; i < 2; i++) {
            int l = tid + i * 256;          // 0..511
            int m = l >> 2;
            int kq = l & 3;                 // k_local = kq*4 .. +3
            float4 v = *(const float4*)(A + (long long)(row0 + m) * K + k0 + kq * 4);
            int mt = m >> 4, row = m & 15;
            int k8 = kq >> 1;
            int reg = (row >> 3) + ((kq & 1) << 1);
            int base = (((k8 * 8 + mt) * 32) + (row & 7) * 4) * 4 + reg;
            As[base + 0]  = f2tf32(v.x);
            As[base + 4]  = f2tf32(v.y);
            As[base + 8]  = f2tf32(v.z);
            As[base + 12] = f2tf32(v.w);
        }
        // ---- B tile 16x64 -> fragment-order smem (1 float4 per thread) ----
        {
            int k_local = tid >> 4;
            int nq = tid & 15;              // n_local = nq*4 .. +3
            float4 v;
            if (nvec) {
                v = *(const float4*)(B + (long long)(k0 + k_local) * N + col0 + nq * 4);
            } else {
                const float* bp = B + (long long)(k0 + k_local) * N;
                int n0 = col0 + nq * 4;
                v.x = (n0 + 0 < N) ? bp[n0 + 0] : 0.f;
                v.y = (n0 + 1 < N) ? bp[n0 + 1] : 0.f;
                v.z = (n0 + 2 < N) ? bp[n0 + 2] : 0.f;
                v.w = (n0 + 3 < N) ? bp[n0 + 3] : 0.f;
            }
            int k8 = k_local >> 3;
            int reg = (k_local >> 2) & 1;
            int ktig = k_local & 3;
            int nt = (nq * 4) >> 3;
            int gbase = (nq * 4) & 7;
            int base = (((k8 * 8 + nt) * 32) + gbase * 4 + ktig) * 2 + reg;
            Bs[base + 0]  = f2tf32(v.x);
            Bs[base + 8]  = f2tf32(v.y);
            Bs[base + 16] = f2tf32(v.z);
            Bs[base + 24] = f2tf32(v.w);
        }
        __syncthreads();
        // ---- compute: 2 k8-slices x (2 m-tiles x 4 n-tiles) HMMAs ----
        #pragma unroll
        for (int k8 = 0; k8 < 2; k8++) {
            uint32_t a[2][4];
            #pragma unroll
            for (int mi = 0; mi < 2; mi++) {
                int mt = wm * 2 + mi;
                *(uint4*)a[mi] = *(const uint4*)&As[((k8 * 8 + mt) * 32 + lane) * 4];
            }
            uint32_t b[4][2];
            #pragma unroll
            for (int ni = 0; ni < 4; ni++) {
                int nt = wn * 4 + ni;
                *(uint2*)b[ni] = *(const uint2*)&Bs[((k8 * 8 + nt) * 32 + lane) * 2];
            }
            #pragma unroll
            for (int mi = 0; mi < 2; mi++)
                #pragma unroll
                for (int ni = 0; ni < 4; ni++)
                    mma_tf32(acc[mi][ni], a[mi], b[ni]);
        }
        __syncthreads();
    }

    // ---- epilogue ----
    #pragma unroll
    for (int mi = 0; mi < 2; mi++) {
        #pragma unroll
        for (int ni = 0; ni < 4; ni++) {
            int m_base = row0 + wm * 32 + mi * 16 + groupID;
            int n_base = col0 + wn * 32 + ni * 8 + tig * 2;
            #pragma unroll
            for (int r = 0; r < 4; r++) {
                int gm = m_base + ((r >> 1) << 3);
                int gn = n_base + (r & 1);
                if (gn >= N) continue;
                float v = acc[mi][ni][r];
                if (MODE == 0) {
                    if (bias) v += biasScale * bias[gn];
                    C[(long long)gm * N + gn] = v;
                } else {
                    long long br = (long long)(gm >> 5) * biasStride + gn;
                    C [(long long)gm * N + gn] = tanhf(v + bias [br]);
                    C2[(long long)gm * N + gn] = tanhf(v + bias2[br]);
                }
            }
        }
    }
}

__global__ void reduce_add_kernel(const float* __restrict__ src, float* __restrict__ dst,
                                  int parts, long long len)
{
    long long i = (long long)blockIdx.x * 256 + threadIdx.x;
    if (i >= len) return;
    float s = 0.f;
    for (int p = 0; p < parts; p++) s += src[(long long)p * len + i];
    dst[i] = s;
}

// ---------------- stage kernels ----------------
__global__ void rep_kernel(const float* __restrict__ seq, const int* __restrict__ ep)
{
    int bn = blockIdx.x;
    int b = bn / NENT, n = bn % NENT;
    int e0 = ep[(b * NENT + n) * MENT + 0];
    int e1 = ep[(b * NENT + n) * MENT + 1];
    int e2 = ep[(b * NENT + n) * MENT + 2];
    int e3 = ep[(b * NENT + n) * MENT + 3];
    const float* sb = seq + (long long)b * SEQ * HID;
    for (int h = threadIdx.x; h < HID; h += blockDim.x) {
        float v0 = sb[(long long)e0 * HID + h];
        float v1 = sb[(long long)e1 * HID + h];
        float v2 = sb[(long long)e2 * HID + h];
        float v3 = sb[(long long)e3 * HID + h];
        float m = fmaxf(fmaxf(v0, v1), fmaxf(v2, v3));
        float s = expf(v0 - m) + expf(v1 - m) + expf(v2 - m) + expf(v3 - m);
        d_rep[(b * NENT + n) * HID + h] = m + logf(s);
    }
}

__global__ void packA_kernel(const float* __restrict__ A_bl)
{
    int idx = blockIdx.x * 256 + threadIdx.x;
    if (idx >= WD * PP) return;
    int o = idx / PP, pq = idx % PP;
    d_Ablt[pq * WD + o] = A_bl[idx];
}

__global__ void packW_kernel(const float* __restrict__ W_s, const float* __restrict__ W_o)
{
    int idx = blockIdx.x * 256 + threadIdx.x;
    if (idx >= WD * WD) return;
    int k = idx / WD, j = idx % WD;
    d_Wso[(long long)k * (2 * WD) + j]      = W_s[idx];
    d_Wso[(long long)k * (2 * WD) + WD + j] = W_o[idx];
}

__global__ void ga_kernel(const float* __restrict__ att, const int* __restrict__ ep)
{
    int b = blockIdx.z;
    int n = blockIdx.y / HEADS, h = blockIdx.y % HEADS;
    int s = blockIdx.x * blockDim.x + threadIdx.x;
    const float* ab = att + ((long long)(b * HEADS + h)) * SEQ * SEQ;
    float a = 0.f;
    #pragma unroll
    for (int m = 0; m < MENT; m++) {
        int e = ep[(b * NENT + n) * MENT + m];
        a += ab[(long long)e * SEQ + s];
    }
    d_ga[((long long)((b * NENT + n) * HEADS + h)) * SEQ + s] = a;
}

__global__ __launch_bounds__(256) void pa_kernel()
{
    int b = blockIdx.y;
    int ij = blockIdx.x;
    int i = ij >> 5, j = ij & 31;
    const float* gi = d_ga + ((long long)(b * NENT + i)) * HEADS * SEQ;
    const float* gj = d_ga + ((long long)(b * NENT + j)) * HEADS * SEQ;
    int tid = threadIdx.x;
    float acc[4];
    float lsum = 0.f;
    #pragma unroll
    for (int r = 0; r < 4; r++) {
        int s = r * 256 + tid;
        float a = 0.f;
        #pragma unroll
        for (int h = 0; h < HEADS; h++)
            a += gi[h * SEQ + s] * gj[h * SEQ + s];
        acc[r] = a;
        lsum += a;
    }
    __shared__ float red[256];
    red[tid] = lsum;
    __syncthreads();
    for (int off = 128; off > 0; off >>= 1) {
        if (tid < off) red[tid] += red[tid + off];
        __syncthreads();
    }
    float inv = 1.0f / red[0];
    float* po = d_pa + ((long long)(b * NPAIR + ij)) * SEQ;
    #pragma unroll
    for (int r = 0; r < 4; r++)
        po[r * 256 + tid] = acc[r] * inv;
}

__global__ __launch_bounds__(256) void P_kernel()
{
    __shared__ float zs[WD], zo[WD];
    long long row = blockIdx.x;
    for (int w = threadIdx.x; w < WD; w += 256) {
        zs[w] = d_Zs[row * WD + w];
        zo[w] = d_Zo[row * WD + w];
    }
    __syncthreads();
    int t = threadIdx.x;
    if (t < PP) {
        int p = t / DD, q = t % DD;
        float a = 0.f;
        #pragma unroll
        for (int k = 0; k < SPLITK; k++)
            a += zs[p * SPLITK + k] * zo[q * SPLITK + k];
        d_P[row * PP + t] = a;
    }
}

__global__ __launch_bounds__(256) void e_kernel(const float* __restrict__ v_attn)
{
    int row = blockIdx.x;
    int tid = threadIdx.x;
    float val = tanhf(d_t[(long long)row * AD + tid]) * v_attn[tid];
    __shared__ float red[256];
    red[tid] = val;
    __syncthreads();
    for (int off = 128; off > 0; off >>= 1) {
        if (tid < off) red[tid] += red[tid + off];
        __syncthreads();
    }
    if (tid == 0) d_e[row] = red[0];
}

__global__ __launch_bounds__(1024) void softmax_kernel()
{
    int b = blockIdx.x;
    int tid = threadIdx.x;
    int w = tid >> 5, lane = tid & 31;
    const float* eb = d_e + b * NPAIR;
    float v = eb[w * 32 + lane];
    float m = v;
    for (int o = 16; o > 0; o >>= 1) m = fmaxf(m, __shfl_xor_sync(~0u, m, o));
    float ex = expf(v - m);
    float s = ex;
    for (int o = 16; o > 0; o >>= 1) s += __shfl_xor_sync(~0u, s, o);
    d_arow[b * NPAIR + w * 32 + lane] = ex / s;
    float v2 = eb[lane * 32 + w];
    float m2 = v2;
    for (int o = 16; o > 0; o >>= 1) m2 = fmaxf(m2, __shfl_xor_sync(~0u, m2, o));
    float ex2 = expf(v2 - m2);
    float s2 = ex2;
    for (int o = 16; o > 0; o >>= 1) s2 += __shfl_xor_sync(~0u, s2, o);
    d_acol[b * NPAIR + lane * 32 + w] = ex2 / s2;
}

__global__ void rowcolC_kernel()
{
    int b = blockIdx.y, n = blockIdx.x;
    int c = threadIdx.x;
    if (c >= NC) return;
    const float* gc = d_gclf + (long long)b * NPAIR * NC;
    float rs = 0.f, cs = 0.f;
    #pragma unroll 4
    for (int k = 0; k < NENT; k++) {
        rs += d_arow[b * NPAIR + n * 32 + k] * gc[(long long)(n * 32 + k) * NC + c];
        cs += d_acol[b * NPAIR + k * 32 + n] * gc[(long long)(k * 32 + n) * NC + c];
    }
    d_rgcg[(b * NENT + n) * NC + c] = rs;
    d_rgcg[(BATCH * NENT + b * NENT + n) * NC + c] = cs;
}

__global__ void final_kernel(const float* __restrict__ clf_b, float* __restrict__ out)
{
    long long idx = (long long)blockIdx.x * blockDim.x + threadIdx.x;
    const long long total = (long long)BATCH * NPAIR * NC;
    if (idx >= total) return;
    int c = (int)(idx % NC);
    long long rb = idx / NC;
    int ij = (int)(rb % NPAIR);
    int b = (int)(rb / NPAIR);
    int i = ij >> 5, j = ij & 31;
    out[idx] = d_gclf[idx]
             + d_rgcg[(b * NENT + i) * NC + c]
             + d_rgcg[(BATCH * NENT + b * NENT + j) * NC + c]
             + clf_b[c];
}

// ---------------- host launch ----------------
extern "C" void kernel_launch(void* const* d_in, const int* in_sizes, int n_in,
                              void* d_out, int out_size)
{
    const float* seq    = (const float*)d_in[0];
    const float* att    = (const float*)d_in[1];
    const int*   ep     = (const int*)  d_in[2];
    const float* W_s    = (const float*)d_in[3];
    const float* W_o    = (const float*)d_in[4];
    const float* W_c    = (const float*)d_in[5];
    const float* A_bl   = (const float*)d_in[6];
    const float* b_bl   = (const float*)d_in[7];
    const float* W_attn = (const float*)d_in[8];
    const float* v_attn = (const float*)d_in[9];
    const float* clf_W  = (const float*)d_in[10];
    const float* clf_b  = (const float*)d_in[11];
    float* out = (float*)d_out;

    float *p_rep, *p_rso, *p_Wso, *p_pa, *p_ctxh, *p_Zs, *p_Zo, *p_P, *p_Ablt,
          *p_g, *p_t, *p_gclf, *p_part;
    cudaGetSymbolAddress((void**)&p_rep,  d_rep);
    cudaGetSymbolAddress((void**)&p_rso,  d_rso);
    cudaGetSymbolAddress((void**)&p_Wso,  d_Wso);
    cudaGetSymbolAddress((void**)&p_pa,   d_pa);
    cudaGetSymbolAddress((void**)&p_ctxh, d_ctxh);
    cudaGetSymbolAddress((void**)&p_Zs,   d_Zs);
    cudaGetSymbolAddress((void**)&p_Zo,   d_Zo);
    cudaGetSymbolAddress((void**)&p_P,    d_P);
    cudaGetSymbolAddress((void**)&p_Ablt, d_Ablt);
    cudaGetSymbolAddress((void**)&p_g,    d_g);
    cudaGetSymbolAddress((void**)&p_t,    d_t);
    cudaGetSymbolAddress((void**)&p_gclf, d_gclf);
    cudaGetSymbolAddress((void**)&p_part, d_part);

    // 1. entity reps
    rep_kernel<<<BATCH * NENT, 256>>>(seq, ep);
    // 2-3. packs
    packA_kernel<<<(WD * PP + 255) / 256, 256>>>(A_bl);
    packW_kernel<<<(WD * WD + 255) / 256, 256>>>(W_s, W_o);
    // 4. entity attention gather
    {
        dim3 grid(SEQ / 256, NENT * HEADS, BATCH);
        ga_kernel<<<grid, 256>>>(att, ep);
    }
    // 5. pairwise localized attention
    {
        dim3 grid(NPAIR, BATCH);
        pa_kernel<<<grid, 256>>>();
    }
    // 6. ctxh = pa @ seq  (batched)  [1024,768,1024] x4  <- ncu target
    {
        dim3 grid(WD / 64, NPAIR / 128, BATCH);
        mma_gemm<0><<<grid, 256>>>(p_pa, seq, p_ctxh, nullptr,
                                   NPAIR, HID, SEQ,
                                   (long long)NPAIR * SEQ, (long long)SEQ * HID,
                                   (long long)NPAIR * HID,
                                   1, 0, nullptr, 0.f, nullptr, 0);
    }
    // 7. rso partials = rep @ [W_s|W_o]  (split-K 6)  [128,1536,768]
    {
        dim3 grid((2 * WD) / 64, 1, 6);
        mma_gemm<0><<<grid, 256>>>(p_rep, p_Wso, p_part, nullptr,
                                   BATCH * NENT, 2 * WD, HID, 0, 0, 0,
                                   6, (long long)BATCH * NENT * 2 * WD,
                                   nullptr, 0.f, nullptr, 0);
    }
    // 8. reduce rso
    reduce_add_kernel<<<(BATCH * NENT * 2 * WD + 255) / 256, 256>>>(
        p_part, p_rso, 6, (long long)BATCH * NENT * 2 * WD);
    // 9. fused: Zs/Zo = tanh(rso[i] + ctxh @ W_c)  [4096,768,768]
    {
        dim3 grid(WD / 64, (BATCH * NPAIR) / 128, 1);
        mma_gemm<1><<<grid, 256>>>(p_ctxh, W_c, p_Zs, p_Zo,
                                   BATCH * NPAIR, WD, HID, 0, 0, 0,
                                   1, 0, p_rso, 0.f, p_rso + WD, 2 * WD);
    }
    // 10. P
    P_kernel<<<BATCH * NPAIR, 256>>>();
    // 11. g = P @ A_bl^T + 64*b_bl  [4096,768,144]
    {
        dim3 grid(WD / 64, (BATCH * NPAIR) / 128, 1);
        mma_gemm<0><<<grid, 256>>>(p_P, p_Ablt, p_g, nullptr,
                                   BATCH * NPAIR, WD, PP, 0, 0, 0,
                                   1, 0, b_bl, (float)SPLITK, nullptr, 0);
    }
    // 12. t = g @ W_attn  [4096,256,768]
    {
        dim3 grid(AD / 64, (BATCH * NPAIR) / 128, 1);
        mma_gemm<0><<<grid, 256>>>(p_g, W_attn, p_t, nullptr,
                                   BATCH * NPAIR, AD, WD, 0, 0, 0,
                                   1, 0, nullptr, 0.f, nullptr, 0);
    }
    // 13. e = tanh(t) . v_attn
    e_kernel<<<BATCH * NPAIR, 256>>>(v_attn);
    // 14. softmax
    softmax_kernel<<<BATCH, 1024>>>();
    // 15. gclf partials = g @ clf_W (split-K 4)  [4096,97,768]
    {
        long long len = (long long)BATCH * NPAIR * NC;
        dim3 grid((NC + 63) / 64, (BATCH * NPAIR) / 128, 4);
        mma_gemm<0><<<grid, 256>>>(p_g, clf_W, p_part, nullptr,
                                   BATCH * NPAIR, NC, WD, 0, 0, 0,
                                   4, len, nullptr, 0.f, nullptr, 0);
        reduce_add_kernel<<<(unsigned)((len + 255) / 256), 256>>>(p_part, p_gclf, 4, len);
    }
    // 16. axis-attention residual folded through clf_W
    {
        dim3 grid(NENT, BATCH);
        rowcolC_kernel<<<grid, 128>>>();
    }
    // 17. out
    {
        long long total = (long long)BATCH * NPAIR * NC;
        final_kernel<<<(unsigned)((total + 255) / 256), 256>>>(clf_b, out);
    }
}